// round 7
// baseline (speedup 1.0000x reference)
#include <cuda_runtime.h>

#define N       4096
#define THREADS 128
#define PAD(i)  ((i) + ((i) >> 5))
#define SMW     (4096 + 128)

// Sign bitmask: bit e of g_smask[e>>5] = (s[e] < 0). 128 words, built per call.
__device__ unsigned g_smask[N / 32];

__global__ void pack_signs(const float* __restrict__ s)
{
    int i = blockIdx.x * blockDim.x + threadIdx.x;
    unsigned b = __ballot_sync(0xffffffffu, __float_as_int(s[i]) < 0);
    if ((threadIdx.x & 31) == 0) g_smask[i >> 5] = b;
}

__global__ __launch_bounds__(THREADS, 8)
void fwht_kernel(const float* __restrict__ x,
                 float* __restrict__ out)
{
    __shared__ float sm[SMW];

    const int row  = blockIdx.x;
    const int t    = threadIdx.x;   // 0..127
    const int lane = t & 31;
    const int w    = t >> 5;        // 0..3

    // ---- load 32 contiguous elements ----
    // initial layout: i[4:0]=reg, i[9:5]=lane, i[11:10]=w
    float v[32];
    const float4* xr = reinterpret_cast<const float4*>(x + (size_t)row * N + t * 32);
    #pragma unroll
    for (int j = 0; j < 8; j++) {
        float4 a = xr[j];
        v[4*j+0] = a.x; v[4*j+1] = a.y; v[4*j+2] = a.z; v[4*j+3] = a.w;
    }

    // ---- apply signs via bitmask XOR (one word per thread: elements t*32+k) ----
    {
        const unsigned m = g_smask[t];
        #pragma unroll
        for (int k = 0; k < 32; k++)
            v[k] = __int_as_float(__float_as_int(v[k]) ^
                                  (int)((m << (31 - k)) & 0x80000000u));
    }

    // ---- stage 1: FWHT over reg bits i[4:0], 5 levels ----
    #pragma unroll
    for (int m = 1; m < 32; m <<= 1) {
        #pragma unroll
        for (int r = 0; r < 32; r++) {
            if ((r & m) == 0) {
                float a = v[r], b = v[r | m];
                v[r]     = a + b;
                v[r | m] = a - b;
            }
        }
    }

    // ---- stage 2: 2 half-exchange shuffle levels (i5 then i6) ----
    // Each level swaps roles of reg bit 4 and the lane bit.
    // After: regs = {i0,i1,i2,i3, i6}, lane = {i4,i5,i7,i8,i9}, w = i[11:10].
    #pragma unroll
    for (int mm = 1; mm < 4; mm <<= 1) {
        const bool  lo  = (lane & mm) == 0;
        const float sgn = lo ? 1.0f : -1.0f;
        #pragma unroll
        for (int r = 0; r < 16; r++) {
            float keep = lo ? v[r]      : v[r + 16];
            float send = lo ? v[r + 16] : v[r];
            float recv = __shfl_xor_sync(0xffffffffu, send, mm);
            v[r]      = keep + recv;
            v[r + 16] = (keep - recv) * sgn;
        }
    }

    // ---- transpose ----
    // smem address map (weights chosen conflict-free for BOTH patterns):
    // a = i4 + i5<<1 + i7<<2 + i8<<3 + i9<<4 + i6<<5 + i0<<6 + i1<<7 + i2<<8
    //   + i3<<9 + i10<<10 + i11<<11
    // write: lane bits {i4,i5,i7,i8,i9} -> a[4:0]  => bank = lane + const
    const int wb = lane | (w << 10);
    #pragma unroll
    for (int r = 0; r < 32; r++) {
        int a = wb | ((r >> 4) << 5) | ((r & 15) << 6);   // r4=i6, r[3:0]=i[3:0]
        sm[PAD(a)] = v[r];
    }
    __syncthreads();

    // read: thread lane' = i[4:0], w' = {i5,i6}; regs rp = {i7,i8,i9,i10,i11}
    // a = lane'4 + w'0<<1 + rp0<<2 + rp1<<3 + rp2<<4 + w'1<<5 + lane'0<<6
    //   + lane'1<<7 + lane'2<<8 + lane'3<<9 + rp3<<10 + rp4<<11
    // varying lane bank weights: {1,2,4,8,16} -> conflict-free
    const int rb = (lane >> 4) | ((w & 1) << 1) | ((w >> 1) << 5) | ((lane & 15) << 6);
    float u[32];
    #pragma unroll
    for (int rp = 0; rp < 32; rp++) {
        int a = rb | ((rp & 7) << 2) | ((rp >> 3) << 10);
        u[rp] = sm[PAD(a)];
    }

    // ---- stage 3: FWHT over remaining bits i[11:7] = rp[4:0], 5 levels ----
    #pragma unroll
    for (int m = 1; m < 32; m <<= 1) {
        #pragma unroll
        for (int rp = 0; rp < 32; rp++) {
            if ((rp & m) == 0) {
                float a = u[rp], b = u[rp | m];
                u[rp]     = a + b;
                u[rp | m] = a - b;
            }
        }
    }

    // ---- scaled, fully-coalesced store (32 contiguous floats per warp per rp) ----
    const float scale = 0.015625f;   // 1/sqrt(4096)
    float* orow = out + (size_t)row * N;
    const int ob = (w << 5) | lane;  // o = lane | w<<5 | rp<<7
    #pragma unroll
    for (int rp = 0; rp < 32; rp++)
        orow[ob | (rp << 7)] = u[rp] * scale;
}

extern "C" void kernel_launch(void* const* d_in, const int* in_sizes, int n_in,
                              void* d_out, int out_size)
{
    const float* x = (const float*)d_in[0];
    const float* s = (const float*)d_in[1];
    float* out     = (float*)d_out;

    pack_signs<<<N / 1024, 1024>>>(s);

    const int rows = in_sizes[0] / N;   // 16384
    fwht_kernel<<<rows, THREADS>>>(x, out);
}